// round 11
// baseline (speedup 1.0000x reference)
#include <cuda_runtime.h>
#include <cuda_fp16.h>
#include <cstdint>

// ---------------- problem constants ----------------
#define BATCH 32
#define CH    256
#define HH    56
#define WW    56
#define HO    28
#define WO    28
#define NPIX  (BATCH*HH*WW)      // 100352 valid output pixels
#define PROW  58                 // padded row width
#define PIMG  (58*58)            // padded pixels per image = 3364
#define MT_PER_IMG 26            // f-tiles per image (covers 3328 >= 3248)
#define NTILES (2*MT_PER_IMG*BATCH)   // 1664
#define NPCTA  296               // persistent CTAs (2 per SM on 148 SMs)

// conv tiling: CTA M=128 flat pixels x N=128 ch, K-chunk 32 per stage
#define NT        128
#define AROWS     130            // 128 pixels + 2 shift halo
#define RSTRB     80             // smem row stride bytes (40 halves)
#define RSTRH     40
#define AOFF      0
#define BOFF      (AROWS*RSTRB)                        // 10400
#define STAGE     ((BOFF + 384*RSTRB + 127) & ~127)    // 41216
#define DSMEM     (2*STAGE)                            // 82432 -> 2 CTAs/SM

// ---------------- static scratch (zero-initialized) ----------------
__device__ __align__(128) __half g_xpad[(size_t)BATCH*PIMG*CH + 32768]; // [n][f][c]
__device__ __align__(128) __half g_wpack[9*256*256];                    // [rs][o][c]
__device__ __align__(128) __half g_ybuf[(size_t)NPIX*CH];               // NHWC conv out
__device__ float g_sum[256], g_sumsq[256];

// ---------------- helpers ----------------
__device__ __forceinline__ uint32_t su32(const void* p) {
    uint32_t a;
    asm("{.reg .u64 t; cvta.to.shared.u64 t, %1; cvt.u32.u64 %0, t;}" : "=r"(a) : "l"(p));
    return a;
}
__device__ __forceinline__ void cp16(uint32_t dst, const void* src) {
    asm volatile("cp.async.cg.shared.global [%0], [%1], 16;" :: "r"(dst), "l"(src));
}

// ---------------------------------------------------------------------------
// Kernel 1: pack weights -> sign fp16 [rs][o][c]; block 0 zeroes stats
// ---------------------------------------------------------------------------
__global__ __launch_bounds__(256) void pack_w_kernel(const float* __restrict__ W)
{
    int idx = blockIdx.x * 256 + threadIdx.x;     // 0 .. 589823
    int c  = idx & 255;
    int o  = (idx >> 8) & 255;
    int rs = idx >> 16;
    int r  = rs / 3;
    int s  = rs - 3 * r;
    float v = W[(((size_t)o * 256 + c) * 3 + r) * 3 + s];
    float sv = (v > 0.f) ? 1.f : ((v < 0.f) ? -1.f : 0.f);
    g_wpack[idx] = __float2half(sv);
    if (blockIdx.x == 0) {
        g_sum[threadIdx.x]   = 0.f;
        g_sumsq[threadIdx.x] = 0.f;
    }
}

// ---------------------------------------------------------------------------
// Kernel 2: transpose-pack x NCHW fp32 -> flat padded [n][(h+1)*58+(w+1)][c]
// ---------------------------------------------------------------------------
__global__ __launch_bounds__(256) void pack_x_kernel(const float* __restrict__ x)
{
    __shared__ __half sm[256][58];
    const int h = blockIdx.x, n = blockIdx.y;
    const int wi = threadIdx.x & 63, cb = threadIdx.x >> 6;   // cb 0..3
    if (wi < 56) {
        const float* src = x + (((size_t)n * 256 + cb) * 56 + h) * 56 + wi;
        #pragma unroll 8
        for (int c8 = 0; c8 < 64; c8++) {
            sm[c8 * 4 + cb][wi] = __float2half(src[(size_t)c8 * 4 * 56 * 56]);
        }
    }
    __syncthreads();
    for (int chunk = threadIdx.x; chunk < 56 * 32; chunk += 256) {
        int w = chunk >> 5, cq = chunk & 31;
        __half tmp[8];
        #pragma unroll
        for (int j = 0; j < 8; j++) tmp[j] = sm[cq * 8 + j][w];
        *(uint4*)(g_xpad + ((size_t)n * PIMG + (h + 1) * PROW + (w + 1)) * CH + cq * 8)
            = *(uint4*)tmp;
    }
}

// dummy: positions conv as launch #4 so ncu's fixed sample window hits it
__global__ void dummy_kernel() {}

// ---------------------------------------------------------------------------
// Kernel 3: persistent conv. 296 CTAs, each processes ~5-6 tiles with a
// continuous cross-tile cp.async pipeline (prologue/epilogue hidden).
// CTA tile: M=128 flat pixels x N=128 ch; 24 stages (3 h-taps x 8 x 32ch).
// ---------------------------------------------------------------------------
__global__ __launch_bounds__(256, 2) void conv_kernel()
{
    extern __shared__ __align__(128) char dsm[];
    __shared__ float sm_s1[128];
    __shared__ float sm_s2[128];

    const int tid = threadIdx.x;
    const int wid = tid >> 5, lane = tid & 31;
    const int g = lane >> 2, t = lane & 3;
    const int warp_m = wid & 1;                // 64 flat pixels each
    const int warp_n = wid >> 1;               // 32 channels each

    if (tid < 128) { sm_s1[tid] = 0.f; sm_s2[tid] = 0.f; }
    __syncthreads();

    float acc[4][4][4];
    #pragma unroll
    for (int a = 0; a < 4; a++)
        #pragma unroll
        for (int b = 0; b < 4; b++)
            #pragma unroll
            for (int c = 0; c < 4; c++) acc[a][b][c] = 0.f;

    auto decode = [](int tl, int& n0, int& f0, int& nb) {
        n0 = (tl & 1) << 7;
        int rest = tl >> 1;
        nb = rest / MT_PER_IMG;
        f0 = (rest - nb * MT_PER_IMG) << 7;
    };

    // load one (tile, stage) pair; slot parity = stage parity (24 even)
    auto load_stage = [&](int n0, int f0, int nb, int st) {
        char* sb = dsm + (st & 1) * STAGE;
        const int r = st >> 3, kb = st & 7;
        const __half* xp = g_xpad + (size_t)nb * PIMG * CH;
        const int pix0 = f0 + r * PROW;
        #pragma unroll 1
        for (int i = tid; i < AROWS * 4; i += 256) {
            int row = i >> 2, q = i & 3;
            cp16(su32(sb + AOFF + row * RSTRB + q * 16),
                 xp + (size_t)(pix0 + row) * CH + kb * 32 + q * 8);
        }
        const __half* wp = g_wpack + (size_t)(r * 3) * 65536 + (size_t)n0 * 256 + kb * 32;
        #pragma unroll 1
        for (int i = tid; i < 1536; i += 256) {
            int tap = i >> 9, rem = i & 511, nn = rem >> 2, q = rem & 3;
            cp16(su32(sb + BOFF + (tap * 128 + nn) * RSTRB + q * 16),
                 wp + (size_t)tap * 65536 + (size_t)nn * 256 + q * 8);
        }
    };

    auto compute = [&](int st) {
        const char* sb = dsm + (st & 1) * STAGE;
        const __half* sA = (const __half*)(sb + AOFF);
        const __half* sB = (const __half*)(sb + BOFF);
        #pragma unroll
        for (int s = 0; s < 3; s++) {
            #pragma unroll
            for (int kk = 0; kk < 2; kk++) {
                const int c0 = kk * 16 + 2 * t;
                uint32_t af[4][4];
                #pragma unroll
                for (int mt = 0; mt < 4; mt++) {
                    int row = warp_m * 64 + mt * 16 + g + s;
                    af[mt][0] = *(const uint32_t*)(sA + row * RSTRH + c0);
                    af[mt][1] = *(const uint32_t*)(sA + (row + 8) * RSTRH + c0);
                    af[mt][2] = *(const uint32_t*)(sA + row * RSTRH + c0 + 8);
                    af[mt][3] = *(const uint32_t*)(sA + (row + 8) * RSTRH + c0 + 8);
                }
                uint32_t bf[4][2];
                #pragma unroll
                for (int nt = 0; nt < 4; nt++) {
                    int nn = s * 128 + warp_n * 32 + nt * 8 + g;
                    bf[nt][0] = *(const uint32_t*)(sB + nn * RSTRH + c0);
                    bf[nt][1] = *(const uint32_t*)(sB + nn * RSTRH + c0 + 8);
                }
                #pragma unroll
                for (int mt = 0; mt < 4; mt++) {
                    #pragma unroll
                    for (int nt = 0; nt < 4; nt++) {
                        float* cacc = acc[mt][nt];
                        asm volatile(
                          "mma.sync.aligned.m16n8k16.row.col.f32.f16.f16.f32 "
                          "{%0,%1,%2,%3}, {%4,%5,%6,%7}, {%8,%9}, {%0,%1,%2,%3};\n"
                          : "+f"(cacc[0]), "+f"(cacc[1]), "+f"(cacc[2]), "+f"(cacc[3])
                          : "r"(af[mt][0]), "r"(af[mt][1]), "r"(af[mt][2]), "r"(af[mt][3]),
                            "r"(bf[nt][0]), "r"(bf[nt][1]));
                    }
                }
            }
        }
    };

    auto epilogue = [&](int n0, int f0, int nb) {
        float s1[4][2], s2[4][2];
        #pragma unroll
        for (int nt = 0; nt < 4; nt++) { s1[nt][0]=s1[nt][1]=s2[nt][0]=s2[nt][1]=0.f; }
        #pragma unroll
        for (int mt = 0; mt < 4; mt++) {
            const int m0 = warp_m * 64 + mt * 16 + g;
            const int fA = f0 + m0;
            const int fB = fA + 8;
            const int hA = (fA * 565) >> 15, wA = fA - hA * PROW;
            const int hB = (fB * 565) >> 15, wB = fB - hB * PROW;
            const bool vA = (wA < 56) && (hA < 56);
            const bool vB = (wB < 56) && (hB < 56);
            __half* pA = g_ybuf + ((size_t)((nb * HH + hA) * WW + wA)) * CH;
            __half* pB = g_ybuf + ((size_t)((nb * HH + hB) * WW + wB)) * CH;
            #pragma unroll
            for (int nt = 0; nt < 4; nt++) {
                const int ch0 = n0 + warp_n * 32 + nt * 8 + 2 * t;
                float f0v = acc[mt][nt][0], f1v = acc[mt][nt][1];
                float f2v = acc[mt][nt][2], f3v = acc[mt][nt][3];
                if (vA) {
                    *(__half2*)(pA + ch0) = __floats2half2_rn(f0v, f1v);
                    s1[nt][0] += f0v;  s2[nt][0] += f0v * f0v;
                    s1[nt][1] += f1v;  s2[nt][1] += f1v * f1v;
                }
                if (vB) {
                    *(__half2*)(pB + ch0) = __floats2half2_rn(f2v, f3v);
                    s1[nt][0] += f2v;  s2[nt][0] += f2v * f2v;
                    s1[nt][1] += f3v;  s2[nt][1] += f3v * f3v;
                }
            }
        }
        #pragma unroll
        for (int nt = 0; nt < 4; nt++) {
            #pragma unroll
            for (int p = 0; p < 2; p++) {
                #pragma unroll
                for (int m = 4; m < 32; m <<= 1) {
                    s1[nt][p] += __shfl_xor_sync(0xffffffffu, s1[nt][p], m);
                    s2[nt][p] += __shfl_xor_sync(0xffffffffu, s2[nt][p], m);
                }
            }
        }
        if (g == 0) {
            #pragma unroll
            for (int nt = 0; nt < 4; nt++) {
                #pragma unroll
                for (int p = 0; p < 2; p++) {
                    int chl = warp_n * 32 + nt * 8 + 2 * t + p;
                    atomicAdd(&sm_s1[chl], s1[nt][p]);
                    atomicAdd(&sm_s2[chl], s2[nt][p]);
                }
            }
        }
        __syncthreads();
        if (tid < 128) {
            atomicAdd(&g_sum[n0 + tid],   sm_s1[tid]);
            atomicAdd(&g_sumsq[n0 + tid], sm_s2[tid]);
            sm_s1[tid] = 0.f; sm_s2[tid] = 0.f;   // re-zero for next tile
        }
    };

    // ---- persistent loop over tiles with continuous pipeline ----
    int cur = blockIdx.x;
    int cn0, cf0, cnb; decode(cur, cn0, cf0, cnb);
    int nxt = cur + NPCTA;
    int nn0 = 0, nf0 = 0, nnb = 0;
    if (nxt < NTILES) decode(nxt, nn0, nf0, nnb);

    load_stage(cn0, cf0, cnb, 0);
    asm volatile("cp.async.commit_group;" ::: "memory");
    load_stage(cn0, cf0, cnb, 1);
    asm volatile("cp.async.commit_group;" ::: "memory");

    while (true) {
        #pragma unroll 1
        for (int st = 0; st < 24; st++) {
            asm volatile("cp.async.wait_group 1;" ::: "memory");
            __syncthreads();                 // stage st visible to all warps
            compute(st);
            __syncthreads();                 // all warps done reading slot st
            int ls = st + 2;
            if (ls < 24)
                load_stage(cn0, cf0, cnb, ls);
            else if (nxt < NTILES)
                load_stage(nn0, nf0, nnb, ls - 24);
            asm volatile("cp.async.commit_group;" ::: "memory");   // may be empty
        }
        epilogue(cn0, cf0, cnb);
        if (nxt >= NTILES) break;
        cur = nxt; cn0 = nn0; cf0 = nf0; cnb = nnb;
        nxt += NPCTA;
        if (nxt < NTILES) decode(nxt, nn0, nf0, nnb);
        #pragma unroll
        for (int a = 0; a < 4; a++)
            #pragma unroll
            for (int b = 0; b < 4; b++)
                #pragma unroll
                for (int c = 0; c < 4; c++) acc[a][b][c] = 0.f;
    }
}

// ---------------------------------------------------------------------------
// Kernel 4: BN finalize + normalize + ReLU + 2x2 maxpool, -> NCHW fp32
// ---------------------------------------------------------------------------
__global__ __launch_bounds__(256) void pool_kernel(float* __restrict__ out,
                                                   const float* __restrict__ gamma,
                                                   const float* __restrict__ beta)
{
    __shared__ float sm[256 * WO];
    const int ho = blockIdx.x;
    const int n  = blockIdx.y;
    const int c  = threadIdx.x;
    const float inv = 1.f / (float)NPIX;
    const float mean = g_sum[c] * inv;
    const float var  = g_sumsq[c] * inv - mean * mean;
    const float sc = gamma[c] * rsqrtf(var + 1e-5f);
    const float sh = beta[c] - mean * sc;
    const __half* b0 = g_ybuf + ((size_t)(n * HH + 2 * ho) * WW) * CH + c;
    const __half* b1 = b0 + (size_t)WW * CH;
    #pragma unroll 4
    for (int wo = 0; wo < WO; wo++) {
        float a0 = __half2float(b0[(size_t)(2 * wo)     * CH]);
        float a1 = __half2float(b0[(size_t)(2 * wo + 1) * CH]);
        float a2 = __half2float(b1[(size_t)(2 * wo)     * CH]);
        float a3 = __half2float(b1[(size_t)(2 * wo + 1) * CH]);
        float r0 = fmaxf(a0 * sc + sh, 0.f);
        float r1 = fmaxf(a1 * sc + sh, 0.f);
        float r2 = fmaxf(a2 * sc + sh, 0.f);
        float r3 = fmaxf(a3 * sc + sh, 0.f);
        sm[c * WO + wo] = fmaxf(fmaxf(r0, r1), fmaxf(r2, r3));
    }
    __syncthreads();
    for (int i = threadIdx.x; i < 256 * WO; i += 256) {
        int cc = i / WO, wo = i % WO;
        out[(((size_t)n * CH + cc) * HO + ho) * WO + wo] = sm[i];
    }
}

// ---------------------------------------------------------------------------
extern "C" void kernel_launch(void* const* d_in, const int* in_sizes, int n_in,
                              void* d_out, int out_size)
{
    const float* x     = (const float*)d_in[0];
    const float* W     = (const float*)d_in[1];
    const float* gamma = (const float*)d_in[2];
    const float* beta  = (const float*)d_in[3];
    float* out = (float*)d_out;

    pack_w_kernel<<<2304, 256>>>(W);
    pack_x_kernel<<<dim3(HH, BATCH), 256>>>(x);
    dummy_kernel<<<1, 32>>>();          // keep conv in ncu's sample slot (#4)

    cudaFuncSetAttribute(conv_kernel, cudaFuncAttributeMaxDynamicSharedMemorySize, DSMEM);
    conv_kernel<<<NPCTA, 256, DSMEM>>>();

    pool_kernel<<<dim3(HO, BATCH), 256>>>(out, gamma, beta);
}

// round 12
// speedup vs baseline: 1.0450x; 1.0450x over previous
#include <cuda_runtime.h>
#include <cuda_fp16.h>
#include <cstdint>

// ---------------- problem constants ----------------
#define BATCH 32
#define CH    256
#define HH    56
#define WW    56
#define HO    28
#define WO    28
#define NPIX  (BATCH*HH*WW)      // 100352 valid output pixels
#define PROW  58                 // padded row width
#define PIMG  (58*58)            // padded pixels per image = 3364
#define MT_PER_IMG 26            // f-tiles per image (covers 3328 >= 3248)

// conv tiling: CTA M=128 flat pixels x N=128 ch, K-chunk 32 per stage
#define NT        128
#define AROWS     130            // 128 pixels + 2 shift halo
#define RSTRB     80             // smem row stride bytes (40 halves)
#define RSTRH     40
#define AOFF      0
#define BOFF      (AROWS*RSTRB)                        // 10400
#define STAGE     ((BOFF + 384*RSTRB + 127) & ~127)    // 41216
#define DSMEM     (2*STAGE)                            // 82432 -> 2 CTAs/SM

// ---------------- static scratch (zero-initialized) ----------------
__device__ __align__(128) __half g_xpad[(size_t)BATCH*PIMG*CH + 32768]; // [n][f][c]
__device__ __align__(128) __half g_wpack[9*256*256];                    // [rs][o][c]
__device__ __align__(128) __half g_ybuf[(size_t)NPIX*CH];               // NHWC conv out
__device__ float g_sum[256], g_sumsq[256];

// ---------------- helpers ----------------
__device__ __forceinline__ uint32_t su32(const void* p) {
    uint32_t a;
    asm("{.reg .u64 t; cvta.to.shared.u64 t, %1; cvt.u32.u64 %0, t;}" : "=r"(a) : "l"(p));
    return a;
}
__device__ __forceinline__ void cp16(uint32_t dst, const void* src) {
    asm volatile("cp.async.cg.shared.global [%0], [%1], 16;" :: "r"(dst), "l"(src));
}

// ---------------------------------------------------------------------------
// Kernel 1 (fused prep): grid (64, 32).
//   bx <  56: transpose-pack x NCHW fp32 -> flat padded [n][(h+1)*58+(w+1)][c]
//   bx >= 56: pack weights -> sign fp16 [rs][o][c]  (256 blocks x 2304 elems)
// ---------------------------------------------------------------------------
__global__ __launch_bounds__(256) void prep_kernel(const float* __restrict__ x,
                                                   const float* __restrict__ W)
{
    __shared__ __half sm[256][58];
    const int bx = blockIdx.x, by = blockIdx.y;

    if (bx >= 56) {                       // ---- weight pack path ----
        const int wb = (bx - 56) * 32 + by;            // 0..255
        if (wb == 0) { g_sum[threadIdx.x] = 0.f; g_sumsq[threadIdx.x] = 0.f; }
        #pragma unroll
        for (int j = 0; j < 9; j++) {
            int idx = wb * 2304 + j * 256 + threadIdx.x;   // < 589824
            int c  = idx & 255;
            int o  = (idx >> 8) & 255;
            int rs = idx >> 16;
            int r  = rs / 3;
            int s  = rs - 3 * r;
            float v = W[(((size_t)o * 256 + c) * 3 + r) * 3 + s];
            float sv = (v > 0.f) ? 1.f : ((v < 0.f) ? -1.f : 0.f);
            g_wpack[idx] = __float2half(sv);
        }
        return;
    }

    // ---- x pack path ----
    const int h = bx, n = by;
    const int wi = threadIdx.x & 63, cb = threadIdx.x >> 6;   // cb 0..3
    if (wi < 56) {
        const float* src = x + (((size_t)n * 256 + cb) * 56 + h) * 56 + wi;
        #pragma unroll 8
        for (int c8 = 0; c8 < 64; c8++) {
            sm[c8 * 4 + cb][wi] = __float2half(src[(size_t)c8 * 4 * 56 * 56]);
        }
    }
    __syncthreads();
    for (int chunk = threadIdx.x; chunk < 56 * 32; chunk += 256) {
        int w = chunk >> 5, cq = chunk & 31;
        __half tmp[8];
        #pragma unroll
        for (int j = 0; j < 8; j++) tmp[j] = sm[cq * 8 + j][w];
        *(uint4*)(g_xpad + ((size_t)n * PIMG + (h + 1) * PROW + (w + 1)) * CH + cq * 8)
            = *(uint4*)tmp;
    }
}

// dummy: positions pool as launch #4 so ncu's fixed sample window hits it
__global__ void dummy_kernel() {}

// ---------------------------------------------------------------------------
// Kernel 2: conv via mma.sync, flat-58 tiling, 2-deep cp.async ring,
// 2 CTAs/SM, fused masked BN stats.  (exact R10 configuration)
// grid (2 ch-tiles, 26 f-tiles, 32 n) = 1664 CTAs, 256 thr (8 warps: 2m x 4n).
// 24 smem stages = 3 h-taps x 8 blocks of 32 in-ch.
// ---------------------------------------------------------------------------
__global__ __launch_bounds__(256, 2) void conv_kernel()
{
    extern __shared__ __align__(128) char dsm[];
    __shared__ float sm_s1[128];
    __shared__ float sm_s2[128];

    const int n0  = blockIdx.x * NT;
    const int f0  = blockIdx.y * 128;          // flat output base
    const int nb  = blockIdx.z;
    const int tid = threadIdx.x;
    const int wid = tid >> 5, lane = tid & 31;
    const int g = lane >> 2, t = lane & 3;
    const int warp_m = wid & 1;                // 64 flat pixels each
    const int warp_n = wid >> 1;               // 32 channels each

    float acc[4][4][4];
    #pragma unroll
    for (int a = 0; a < 4; a++)
        #pragma unroll
        for (int b = 0; b < 4; b++)
            #pragma unroll
            for (int c = 0; c < 4; c++) acc[a][b][c] = 0.f;

    if (tid < 128) { sm_s1[tid] = 0.f; sm_s2[tid] = 0.f; }

    const __half* xp = g_xpad + (size_t)nb * PIMG * CH;

    auto load_stage = [&](int st) {
        char* sb = dsm + (st & 1) * STAGE;
        const int r = st >> 3, kb = st & 7;        // kb: 32-ch block
        const int pix0 = f0 + r * PROW;
        #pragma unroll 1
        for (int i = tid; i < AROWS * 4; i += 256) {
            int row = i >> 2, q = i & 3;
            cp16(su32(sb + AOFF + row * RSTRB + q * 16),
                 xp + (size_t)(pix0 + row) * CH + kb * 32 + q * 8);
        }
        const __half* wp = g_wpack + (size_t)(r * 3) * 65536 + (size_t)n0 * 256 + kb * 32;
        #pragma unroll 1
        for (int i = tid; i < 1536; i += 256) {
            int tap = i >> 9, rem = i & 511, nn = rem >> 2, q = rem & 3;
            cp16(su32(sb + BOFF + (tap * 128 + nn) * RSTRB + q * 16),
                 wp + (size_t)tap * 65536 + (size_t)nn * 256 + q * 8);
        }
        asm volatile("cp.async.commit_group;" ::: "memory");
    };

    auto compute = [&](int st) {
        const char* sb = dsm + (st & 1) * STAGE;
        const __half* sA = (const __half*)(sb + AOFF);
        const __half* sB = (const __half*)(sb + BOFF);
        #pragma unroll
        for (int s = 0; s < 3; s++) {
            #pragma unroll
            for (int kk = 0; kk < 2; kk++) {
                const int c0 = kk * 16 + 2 * t;
                uint32_t af[4][4];
                #pragma unroll
                for (int mt = 0; mt < 4; mt++) {
                    int row = warp_m * 64 + mt * 16 + g + s;
                    af[mt][0] = *(const uint32_t*)(sA + row * RSTRH + c0);
                    af[mt][1] = *(const uint32_t*)(sA + (row + 8) * RSTRH + c0);
                    af[mt][2] = *(const uint32_t*)(sA + row * RSTRH + c0 + 8);
                    af[mt][3] = *(const uint32_t*)(sA + (row + 8) * RSTRH + c0 + 8);
                }
                uint32_t bf[4][2];
                #pragma unroll
                for (int nt = 0; nt < 4; nt++) {
                    int nn = s * 128 + warp_n * 32 + nt * 8 + g;
                    bf[nt][0] = *(const uint32_t*)(sB + nn * RSTRH + c0);
                    bf[nt][1] = *(const uint32_t*)(sB + nn * RSTRH + c0 + 8);
                }
                #pragma unroll
                for (int mt = 0; mt < 4; mt++) {
                    #pragma unroll
                    for (int nt = 0; nt < 4; nt++) {
                        float* cacc = acc[mt][nt];
                        asm volatile(
                          "mma.sync.aligned.m16n8k16.row.col.f32.f16.f16.f32 "
                          "{%0,%1,%2,%3}, {%4,%5,%6,%7}, {%8,%9}, {%0,%1,%2,%3};\n"
                          : "+f"(cacc[0]), "+f"(cacc[1]), "+f"(cacc[2]), "+f"(cacc[3])
                          : "r"(af[mt][0]), "r"(af[mt][1]), "r"(af[mt][2]), "r"(af[mt][3]),
                            "r"(bf[nt][0]), "r"(bf[nt][1]));
                    }
                }
            }
        }
    };

    load_stage(0);
    load_stage(1);
    #pragma unroll 1
    for (int st = 0; st < 24; st++) {
        if (st < 23)
            asm volatile("cp.async.wait_group 1;" ::: "memory");
        else
            asm volatile("cp.async.wait_group 0;" ::: "memory");
        __syncthreads();                 // stage st visible to all warps
        compute(st);
        if (st + 2 < 24) {
            __syncthreads();             // all warps done reading slot st
            load_stage(st + 2);
        }
    }

    // ---- epilogue: acc -> fp16 NHWC (masked) + fused masked BN stats ----
    float s1[4][2], s2[4][2];
    #pragma unroll
    for (int nt = 0; nt < 4; nt++) { s1[nt][0]=s1[nt][1]=s2[nt][0]=s2[nt][1]=0.f; }

    #pragma unroll
    for (int mt = 0; mt < 4; mt++) {
        const int m0 = warp_m * 64 + mt * 16 + g;
        const int fA = f0 + m0;                 // rows g (regs 0,1)
        const int fB = fA + 8;                  // rows g+8 (regs 2,3)
        const int hA = (fA * 565) >> 15, wA = fA - hA * PROW;
        const int hB = (fB * 565) >> 15, wB = fB - hB * PROW;
        const bool vA = (wA < 56) && (hA < 56);
        const bool vB = (wB < 56) && (hB < 56);
        __half* pA = g_ybuf + ((size_t)((nb * HH + hA) * WW + wA)) * CH;
        __half* pB = g_ybuf + ((size_t)((nb * HH + hB) * WW + wB)) * CH;
        #pragma unroll
        for (int nt = 0; nt < 4; nt++) {
            const int ch0 = n0 + warp_n * 32 + nt * 8 + 2 * t;
            float f0v = acc[mt][nt][0], f1v = acc[mt][nt][1];
            float f2v = acc[mt][nt][2], f3v = acc[mt][nt][3];
            if (vA) {
                *(__half2*)(pA + ch0) = __floats2half2_rn(f0v, f1v);
                s1[nt][0] += f0v;  s2[nt][0] += f0v * f0v;
                s1[nt][1] += f1v;  s2[nt][1] += f1v * f1v;
            }
            if (vB) {
                *(__half2*)(pB + ch0) = __floats2half2_rn(f2v, f3v);
                s1[nt][0] += f2v;  s2[nt][0] += f2v * f2v;
                s1[nt][1] += f3v;  s2[nt][1] += f3v * f3v;
            }
        }
    }
    #pragma unroll
    for (int nt = 0; nt < 4; nt++) {
        #pragma unroll
        for (int p = 0; p < 2; p++) {
            #pragma unroll
            for (int m = 4; m < 32; m <<= 1) {
                s1[nt][p] += __shfl_xor_sync(0xffffffffu, s1[nt][p], m);
                s2[nt][p] += __shfl_xor_sync(0xffffffffu, s2[nt][p], m);
            }
        }
    }
    __syncthreads();
    if (g == 0) {
        #pragma unroll
        for (int nt = 0; nt < 4; nt++) {
            #pragma unroll
            for (int p = 0; p < 2; p++) {
                int chl = warp_n * 32 + nt * 8 + 2 * t + p;
                atomicAdd(&sm_s1[chl], s1[nt][p]);
                atomicAdd(&sm_s2[chl], s2[nt][p]);
            }
        }
    }
    __syncthreads();
    if (tid < 128) {
        atomicAdd(&g_sum[n0 + tid],   sm_s1[tid]);
        atomicAdd(&g_sumsq[n0 + tid], sm_s2[tid]);
    }
}

// ---------------------------------------------------------------------------
// Kernel 3: BN finalize + normalize + ReLU + 2x2 maxpool, -> NCHW fp32.
// 256 threads: c2 = tid&127 (channel pair), p = tid>>7 (wo parity).
// Warp loads are 128B contiguous (half2 per thread across 32 channel pairs).
// ---------------------------------------------------------------------------
__global__ __launch_bounds__(256) void pool_kernel(float* __restrict__ out,
                                                   const float* __restrict__ gamma,
                                                   const float* __restrict__ beta)
{
    __shared__ float sm[256 * WO];
    const int ho = blockIdx.x;
    const int n  = blockIdx.y;
    const int c2 = threadIdx.x & 127;      // channel pair: channels 2c2, 2c2+1
    const int p  = threadIdx.x >> 7;       // wo parity

    const float inv = 1.f / (float)NPIX;
    const int ca = 2 * c2, cb2 = 2 * c2 + 1;
    float mean_a = g_sum[ca] * inv,  mean_b = g_sumsq[ca] * inv - mean_a * mean_a;
    float sc_a = gamma[ca] * rsqrtf(mean_b + 1e-5f);
    float sh_a = beta[ca] - mean_a * sc_a;
    float mean_c = g_sum[cb2] * inv, var_c = g_sumsq[cb2] * inv - mean_c * mean_c;
    float sc_b = gamma[cb2] * rsqrtf(var_c + 1e-5f);
    float sh_b = beta[cb2] - mean_c * sc_b;

    const __half2* b0 = (const __half2*)(g_ybuf
                        + ((size_t)(n * HH + 2 * ho) * WW) * CH) + c2;
    const __half2* b1 = b0 + (size_t)WW * (CH / 2);

    #pragma unroll
    for (int k = 0; k < WO / 2; k++) {
        const int wo = 2 * k + p;
        float2 a0 = __half22float2(b0[(size_t)(2 * wo)     * (CH / 2)]);
        float2 a1 = __half22float2(b0[(size_t)(2 * wo + 1) * (CH / 2)]);
        float2 a2 = __half22float2(b1[(size_t)(2 * wo)     * (CH / 2)]);
        float2 a3 = __half22float2(b1[(size_t)(2 * wo + 1) * (CH / 2)]);
        float ra = fmaxf(fmaxf(fmaxf(a0.x, a1.x), fmaxf(a2.x, a3.x)) * sc_a + sh_a, 0.f);
        float rb = fmaxf(fmaxf(fmaxf(a0.y, a1.y), fmaxf(a2.y, a3.y)) * sc_b + sh_b, 0.f);
        // NOTE: max of (v*sc+sh) == (max v)*sc+sh only if sc>0; gamma=1 here but
        // keep exact semantics: apply affine before max.
        float q0a = fmaxf(a0.x * sc_a + sh_a, 0.f), q1a = fmaxf(a1.x * sc_a + sh_a, 0.f);
        float q2a = fmaxf(a2.x * sc_a + sh_a, 0.f), q3a = fmaxf(a3.x * sc_a + sh_a, 0.f);
        ra = fmaxf(fmaxf(q0a, q1a), fmaxf(q2a, q3a));
        float q0b = fmaxf(a0.y * sc_b + sh_b, 0.f), q1b = fmaxf(a1.y * sc_b + sh_b, 0.f);
        float q2b = fmaxf(a2.y * sc_b + sh_b, 0.f), q3b = fmaxf(a3.y * sc_b + sh_b, 0.f);
        rb = fmaxf(fmaxf(q0b, q1b), fmaxf(q2b, q3b));
        sm[ca  * WO + wo] = ra;
        sm[cb2 * WO + wo] = rb;
    }
    __syncthreads();
    for (int i = threadIdx.x; i < 256 * WO; i += 256) {
        int cc = i / WO, wo = i % WO;
        out[(((size_t)n * CH + cc) * HO + ho) * WO + wo] = sm[i];
    }
}

// ---------------------------------------------------------------------------
extern "C" void kernel_launch(void* const* d_in, const int* in_sizes, int n_in,
                              void* d_out, int out_size)
{
    const float* x     = (const float*)d_in[0];
    const float* W     = (const float*)d_in[1];
    const float* gamma = (const float*)d_in[2];
    const float* beta  = (const float*)d_in[3];
    float* out = (float*)d_out;

    prep_kernel<<<dim3(64, BATCH), 256>>>(x, W);

    cudaFuncSetAttribute(conv_kernel, cudaFuncAttributeMaxDynamicSharedMemorySize, DSMEM);
    conv_kernel<<<dim3(2, MT_PER_IMG, BATCH), 256, DSMEM>>>();

    dummy_kernel<<<1, 32>>>();          // pool lands in ncu's sample slot (#4)
    pool_kernel<<<dim3(HO, BATCH), 256>>>(out, gamma, beta);
}

// round 13
// speedup vs baseline: 1.0692x; 1.0232x over previous
#include <cuda_runtime.h>
#include <cuda_fp16.h>
#include <cstdint>

// ---------------- problem constants ----------------
#define BATCH 32
#define CH    256
#define HH    56
#define WW    56
#define HO    28
#define WO    28
#define NPIX  (BATCH*HH*WW)      // 100352 valid output pixels
#define PROW  58                 // padded row width
#define PIMG  (58*58)            // padded pixels per image = 3364
#define MT_PER_IMG 26            // f-tiles per image (covers 3328 >= 3248)

// conv tiling: CTA M=128 flat pixels x N=128 ch, K-chunk 32 per stage
#define NT        128
#define AROWS     130            // 128 pixels + 2 shift halo
#define RSTRB     80             // smem row stride bytes (40 halves)
#define RSTRH     40
#define AOFF      0
#define BOFF      (AROWS*RSTRB)                        // 10400
#define STAGE     ((BOFF + 384*RSTRB + 127) & ~127)    // 41216
#define DSMEM     (2*STAGE)                            // 82432 -> 2 CTAs/SM

// ---------------- static scratch (zero-initialized) ----------------
__device__ __align__(128) __half g_xpad[(size_t)BATCH*PIMG*CH + 32768]; // [n][f][c]
__device__ __align__(128) __half g_wpack[9*256*256];                    // [rs][o][c]
__device__ __align__(128) __half g_ybuf[(size_t)NPIX*CH];               // NHWC conv out
__device__ float g_sum[256], g_sumsq[256];

// ---------------- helpers ----------------
__device__ __forceinline__ uint32_t su32(const void* p) {
    uint32_t a;
    asm("{.reg .u64 t; cvta.to.shared.u64 t, %1; cvt.u32.u64 %0, t;}" : "=r"(a) : "l"(p));
    return a;
}
__device__ __forceinline__ void cp16(uint32_t dst, const void* src) {
    asm volatile("cp.async.cg.shared.global [%0], [%1], 16;" :: "r"(dst), "l"(src));
}

// ---------------------------------------------------------------------------
// Kernel 1 (fused prep, 512 threads): grid (64, 32).
//   bx <  56: transpose-pack x NCHW fp32 -> flat padded [n][(h+1)*58+(w+1)][c]
//   bx >= 56: pack weights -> sign fp16 [rs][o][c]
// ---------------------------------------------------------------------------
__global__ __launch_bounds__(512) void prep_kernel(const float* __restrict__ x,
                                                   const float* __restrict__ W)
{
    __shared__ __half sm[256][58];
    const int bx = blockIdx.x, by = blockIdx.y;
    const int tid = threadIdx.x;

    if (bx >= 56) {                       // ---- weight pack path ----
        const int wb = (bx - 56) * 32 + by;            // 0..255
        if (wb == 0 && tid < 256) { g_sum[tid] = 0.f; g_sumsq[tid] = 0.f; }
        #pragma unroll
        for (int j = 0; j < 4; j++) {
            int idx = wb * 2304 + j * 512 + tid;       // < 589824
            int c  = idx & 255;
            int o  = (idx >> 8) & 255;
            int rs = idx >> 16;
            int r  = rs / 3;
            int s  = rs - 3 * r;
            float v = W[(((size_t)o * 256 + c) * 3 + r) * 3 + s];
            float sv = (v > 0.f) ? 1.f : ((v < 0.f) ? -1.f : 0.f);
            g_wpack[idx] = __float2half(sv);
        }
        if (tid < 256) {
            int idx = wb * 2304 + 2048 + tid;
            int c  = idx & 255;
            int o  = (idx >> 8) & 255;
            int rs = idx >> 16;
            int r  = rs / 3;
            int s  = rs - 3 * r;
            float v = W[(((size_t)o * 256 + c) * 3 + r) * 3 + s];
            float sv = (v > 0.f) ? 1.f : ((v < 0.f) ? -1.f : 0.f);
            g_wpack[idx] = __float2half(sv);
        }
        return;
    }

    // ---- x pack path ----
    const int h = bx, n = by;
    const int wi  = tid & 63;
    const int gid = tid >> 6;                 // 0..7
    const int cb  = gid & 3;                  // channel low bits
    const int seg = gid >> 2;                 // 0..1: half of c8 range
    if (wi < 56) {
        const float* src = x + (((size_t)n * 256 + cb) * 56 + h) * 56 + wi;
        #pragma unroll 8
        for (int c8s = 0; c8s < 32; c8s++) {
            int c8 = seg * 32 + c8s;
            sm[c8 * 4 + cb][wi] = __float2half(src[(size_t)c8 * 4 * 56 * 56]);
        }
    }
    __syncthreads();
    for (int chunk = tid; chunk < 56 * 32; chunk += 512) {
        int w = chunk >> 5, cq = chunk & 31;
        __half tmp[8];
        #pragma unroll
        for (int j = 0; j < 8; j++) tmp[j] = sm[cq * 8 + j][w];
        *(uint4*)(g_xpad + ((size_t)n * PIMG + (h + 1) * PROW + (w + 1)) * CH + cq * 8)
            = *(uint4*)tmp;
    }
}

// ---------------------------------------------------------------------------
// Kernel 2: conv via mma.sync, flat-58 tiling, 2-deep cp.async ring,
// 2 CTAs/SM, fused masked BN stats.  (R10 configuration — at its MMA floor)
// grid (2 ch-tiles, 26 f-tiles, 32 n) = 1664 CTAs, 256 thr (8 warps: 2m x 4n).
// ---------------------------------------------------------------------------
__global__ __launch_bounds__(256, 2) void conv_kernel()
{
    extern __shared__ __align__(128) char dsm[];
    __shared__ float sm_s1[128];
    __shared__ float sm_s2[128];

    const int n0  = blockIdx.x * NT;
    const int f0  = blockIdx.y * 128;          // flat output base
    const int nb  = blockIdx.z;
    const int tid = threadIdx.x;
    const int wid = tid >> 5, lane = tid & 31;
    const int g = lane >> 2, t = lane & 3;
    const int warp_m = wid & 1;                // 64 flat pixels each
    const int warp_n = wid >> 1;               // 32 channels each

    float acc[4][4][4];
    #pragma unroll
    for (int a = 0; a < 4; a++)
        #pragma unroll
        for (int b = 0; b < 4; b++)
            #pragma unroll
            for (int c = 0; c < 4; c++) acc[a][b][c] = 0.f;

    if (tid < 128) { sm_s1[tid] = 0.f; sm_s2[tid] = 0.f; }

    const __half* xp = g_xpad + (size_t)nb * PIMG * CH;

    auto load_stage = [&](int st) {
        char* sb = dsm + (st & 1) * STAGE;
        const int r = st >> 3, kb = st & 7;        // kb: 32-ch block
        const int pix0 = f0 + r * PROW;
        #pragma unroll 1
        for (int i = tid; i < AROWS * 4; i += 256) {
            int row = i >> 2, q = i & 3;
            cp16(su32(sb + AOFF + row * RSTRB + q * 16),
                 xp + (size_t)(pix0 + row) * CH + kb * 32 + q * 8);
        }
        const __half* wp = g_wpack + (size_t)(r * 3) * 65536 + (size_t)n0 * 256 + kb * 32;
        #pragma unroll 1
        for (int i = tid; i < 1536; i += 256) {
            int tap = i >> 9, rem = i & 511, nn = rem >> 2, q = rem & 3;
            cp16(su32(sb + BOFF + (tap * 128 + nn) * RSTRB + q * 16),
                 wp + (size_t)tap * 65536 + (size_t)nn * 256 + q * 8);
        }
        asm volatile("cp.async.commit_group;" ::: "memory");
    };

    auto compute = [&](int st) {
        const char* sb = dsm + (st & 1) * STAGE;
        const __half* sA = (const __half*)(sb + AOFF);
        const __half* sB = (const __half*)(sb + BOFF);
        #pragma unroll
        for (int s = 0; s < 3; s++) {
            #pragma unroll
            for (int kk = 0; kk < 2; kk++) {
                const int c0 = kk * 16 + 2 * t;
                uint32_t af[4][4];
                #pragma unroll
                for (int mt = 0; mt < 4; mt++) {
                    int row = warp_m * 64 + mt * 16 + g + s;
                    af[mt][0] = *(const uint32_t*)(sA + row * RSTRH + c0);
                    af[mt][1] = *(const uint32_t*)(sA + (row + 8) * RSTRH + c0);
                    af[mt][2] = *(const uint32_t*)(sA + row * RSTRH + c0 + 8);
                    af[mt][3] = *(const uint32_t*)(sA + (row + 8) * RSTRH + c0 + 8);
                }
                uint32_t bf[4][2];
                #pragma unroll
                for (int nt = 0; nt < 4; nt++) {
                    int nn = s * 128 + warp_n * 32 + nt * 8 + g;
                    bf[nt][0] = *(const uint32_t*)(sB + nn * RSTRH + c0);
                    bf[nt][1] = *(const uint32_t*)(sB + nn * RSTRH + c0 + 8);
                }
                #pragma unroll
                for (int mt = 0; mt < 4; mt++) {
                    #pragma unroll
                    for (int nt = 0; nt < 4; nt++) {
                        float* cacc = acc[mt][nt];
                        asm volatile(
                          "mma.sync.aligned.m16n8k16.row.col.f32.f16.f16.f32 "
                          "{%0,%1,%2,%3}, {%4,%5,%6,%7}, {%8,%9}, {%0,%1,%2,%3};\n"
                          : "+f"(cacc[0]), "+f"(cacc[1]), "+f"(cacc[2]), "+f"(cacc[3])
                          : "r"(af[mt][0]), "r"(af[mt][1]), "r"(af[mt][2]), "r"(af[mt][3]),
                            "r"(bf[nt][0]), "r"(bf[nt][1]));
                    }
                }
            }
        }
    };

    load_stage(0);
    load_stage(1);
    #pragma unroll 1
    for (int st = 0; st < 24; st++) {
        if (st < 23)
            asm volatile("cp.async.wait_group 1;" ::: "memory");
        else
            asm volatile("cp.async.wait_group 0;" ::: "memory");
        __syncthreads();                 // stage st visible to all warps
        compute(st);
        if (st + 2 < 24) {
            __syncthreads();             // all warps done reading slot st
            load_stage(st + 2);
        }
    }

    // ---- epilogue: acc -> fp16 NHWC (masked) + fused masked BN stats ----
    float s1[4][2], s2[4][2];
    #pragma unroll
    for (int nt = 0; nt < 4; nt++) { s1[nt][0]=s1[nt][1]=s2[nt][0]=s2[nt][1]=0.f; }

    #pragma unroll
    for (int mt = 0; mt < 4; mt++) {
        const int m0 = warp_m * 64 + mt * 16 + g;
        const int fA = f0 + m0;                 // rows g (regs 0,1)
        const int fB = fA + 8;                  // rows g+8 (regs 2,3)
        const int hA = (fA * 565) >> 15, wA = fA - hA * PROW;
        const int hB = (fB * 565) >> 15, wB = fB - hB * PROW;
        const bool vA = (wA < 56) && (hA < 56);
        const bool vB = (wB < 56) && (hB < 56);
        __half* pA = g_ybuf + ((size_t)((nb * HH + hA) * WW + wA)) * CH;
        __half* pB = g_ybuf + ((size_t)((nb * HH + hB) * WW + wB)) * CH;
        #pragma unroll
        for (int nt = 0; nt < 4; nt++) {
            const int ch0 = n0 + warp_n * 32 + nt * 8 + 2 * t;
            float f0v = acc[mt][nt][0], f1v = acc[mt][nt][1];
            float f2v = acc[mt][nt][2], f3v = acc[mt][nt][3];
            if (vA) {
                *(__half2*)(pA + ch0) = __floats2half2_rn(f0v, f1v);
                s1[nt][0] += f0v;  s2[nt][0] += f0v * f0v;
                s1[nt][1] += f1v;  s2[nt][1] += f1v * f1v;
            }
            if (vB) {
                *(__half2*)(pB + ch0) = __floats2half2_rn(f2v, f3v);
                s1[nt][0] += f2v;  s2[nt][0] += f2v * f2v;
                s1[nt][1] += f3v;  s2[nt][1] += f3v * f3v;
            }
        }
    }
    #pragma unroll
    for (int nt = 0; nt < 4; nt++) {
        #pragma unroll
        for (int p = 0; p < 2; p++) {
            #pragma unroll
            for (int m = 4; m < 32; m <<= 1) {
                s1[nt][p] += __shfl_xor_sync(0xffffffffu, s1[nt][p], m);
                s2[nt][p] += __shfl_xor_sync(0xffffffffu, s2[nt][p], m);
            }
        }
    }
    __syncthreads();
    if (g == 0) {
        #pragma unroll
        for (int nt = 0; nt < 4; nt++) {
            #pragma unroll
            for (int p = 0; p < 2; p++) {
                int chl = warp_n * 32 + nt * 8 + 2 * t + p;
                atomicAdd(&sm_s1[chl], s1[nt][p]);
                atomicAdd(&sm_s2[chl], s2[nt][p]);
            }
        }
    }
    __syncthreads();
    if (tid < 128) {
        atomicAdd(&g_sum[n0 + tid],   sm_s1[tid]);
        atomicAdd(&g_sumsq[n0 + tid], sm_s2[tid]);
    }
}

// ---------------------------------------------------------------------------
// Kernel 3: BN finalize + normalize + ReLU + 2x2 maxpool, -> NCHW fp32.
// grid (28 ho, 32 n, 2 ch-halves), 256 threads. 14KB smem/block.
// c2 = tid&63 (channel pair within half), p = tid>>6 (wo mod 4).
// ---------------------------------------------------------------------------
__global__ __launch_bounds__(256) void pool_kernel(float* __restrict__ out,
                                                   const float* __restrict__ gamma,
                                                   const float* __restrict__ beta)
{
    __shared__ float sm[128 * WO];
    const int ho = blockIdx.x;
    const int n  = blockIdx.y;
    const int z  = blockIdx.z;              // channel half
    const int c2 = threadIdx.x & 63;        // pair within half
    const int p  = threadIdx.x >> 6;        // 0..3

    const float inv = 1.f / (float)NPIX;
    const int ca = z * 128 + 2 * c2, cb = ca + 1;
    float mA = g_sum[ca] * inv, vA = g_sumsq[ca] * inv - mA * mA;
    float scA = gamma[ca] * rsqrtf(vA + 1e-5f);
    float shA = beta[ca] - mA * scA;
    float mB = g_sum[cb] * inv, vB = g_sumsq[cb] * inv - mB * mB;
    float scB = gamma[cb] * rsqrtf(vB + 1e-5f);
    float shB = beta[cb] - mB * scB;

    const __half2* b0 = (const __half2*)(g_ybuf
                        + ((size_t)(n * HH + 2 * ho) * WW) * CH) + z * 64 + c2;
    const __half2* b1 = b0 + (size_t)WW * (CH / 2);

    #pragma unroll
    for (int k = 0; k < 7; k++) {
        const int wo = 4 * k + p;
        float2 a0 = __half22float2(b0[(size_t)(2 * wo)     * (CH / 2)]);
        float2 a1 = __half22float2(b0[(size_t)(2 * wo + 1) * (CH / 2)]);
        float2 a2 = __half22float2(b1[(size_t)(2 * wo)     * (CH / 2)]);
        float2 a3 = __half22float2(b1[(size_t)(2 * wo + 1) * (CH / 2)]);
        float q0 = fmaxf(a0.x * scA + shA, 0.f), q1 = fmaxf(a1.x * scA + shA, 0.f);
        float q2 = fmaxf(a2.x * scA + shA, 0.f), q3 = fmaxf(a3.x * scA + shA, 0.f);
        sm[(2 * c2) * WO + wo] = fmaxf(fmaxf(q0, q1), fmaxf(q2, q3));
        float r0 = fmaxf(a0.y * scB + shB, 0.f), r1 = fmaxf(a1.y * scB + shB, 0.f);
        float r2 = fmaxf(a2.y * scB + shB, 0.f), r3 = fmaxf(a3.y * scB + shB, 0.f);
        sm[(2 * c2 + 1) * WO + wo] = fmaxf(fmaxf(r0, r1), fmaxf(r2, r3));
    }
    __syncthreads();
    for (int i = threadIdx.x; i < 128 * WO; i += 256) {
        int cc = i / WO, wo = i % WO;
        out[(((size_t)n * CH + z * 128 + cc) * HO + ho) * WO + wo] = sm[i];
    }
}

// ---------------------------------------------------------------------------
extern "C" void kernel_launch(void* const* d_in, const int* in_sizes, int n_in,
                              void* d_out, int out_size)
{
    const float* x     = (const float*)d_in[0];
    const float* W     = (const float*)d_in[1];
    const float* gamma = (const float*)d_in[2];
    const float* beta  = (const float*)d_in[3];
    float* out = (float*)d_out;

    prep_kernel<<<dim3(64, BATCH), 512>>>(x, W);

    cudaFuncSetAttribute(conv_kernel, cudaFuncAttributeMaxDynamicSharedMemorySize, DSMEM);
    conv_kernel<<<dim3(2, MT_PER_IMG, BATCH), 256, DSMEM>>>();

    pool_kernel<<<dim3(HO, BATCH, 2), 256>>>(out, gamma, beta);
}

// round 14
// speedup vs baseline: 1.1128x; 1.0407x over previous
#include <cuda_runtime.h>
#include <cuda_fp16.h>
#include <cstdint>

// ---------------- problem constants ----------------
#define BATCH 32
#define CH    256
#define HH    56
#define WW    56
#define HO    28
#define WO    28
#define NPIX  (BATCH*HH*WW)      // 100352 valid output pixels
#define PROW  58                 // padded row width
#define PIMG  (58*58)            // padded pixels per image = 3364
#define MT_PER_IMG 26            // f-tiles per image (covers 3328 >= 3248)

// conv tiling: CTA M=128 flat pixels x N=128 ch, K-chunk 32 per stage
#define NT        128
#define AROWS     130            // 128 pixels + 2 shift halo
#define RSTRB     80             // smem row stride bytes (40 halves)
#define RSTRH     40
#define AOFF      0
#define BOFF      (AROWS*RSTRB)                        // 10400
#define STAGE     ((BOFF + 384*RSTRB + 127) & ~127)    // 41216
#define DSMEM     (2*STAGE)                            // 82432 -> 2 CTAs/SM

// prep transpose smem row stride (halves): 264 = 132 words; 16B stores across
// a warp land on all 32 banks (4*wi + 0..3), 16B loads likewise. 16B-aligned.
#define TSTR      264

// ---------------- static scratch (zero-initialized) ----------------
__device__ __align__(128) __half g_xpad[(size_t)BATCH*PIMG*CH + 32768]; // [n][f][c]
__device__ __align__(128) __half g_wpack[9*256*256];                    // [rs][o][c]
__device__ __align__(128) __half g_ybuf[(size_t)NPIX*CH];               // NHWC conv out
__device__ float g_sum[256], g_sumsq[256];

// ---------------- helpers ----------------
__device__ __forceinline__ uint32_t su32(const void* p) {
    uint32_t a;
    asm("{.reg .u64 t; cvta.to.shared.u64 t, %1; cvt.u32.u64 %0, t;}" : "=r"(a) : "l"(p));
    return a;
}
__device__ __forceinline__ void cp16(uint32_t dst, const void* src) {
    asm volatile("cp.async.cg.shared.global [%0], [%1], 16;" :: "r"(dst), "l"(src));
}

// ---------------------------------------------------------------------------
// Kernel 1 (fused prep, 512 threads): grid (64, 32).
//   bx <  56: transpose-pack x NCHW fp32 -> flat padded [n][(h+1)*58+(w+1)][c]
//             (conflict-free smem: thread gathers 8 consecutive channels for
//              one pixel, writes uint4; read-out is contiguous uint4)
//   bx >= 56: pack weights -> sign fp16 [rs][o][c]
// ---------------------------------------------------------------------------
__global__ __launch_bounds__(512) void prep_kernel(const float* __restrict__ x,
                                                   const float* __restrict__ W)
{
    __shared__ __half sm[56][TSTR];          // 29568 B
    const int bx = blockIdx.x, by = blockIdx.y;
    const int tid = threadIdx.x;

    if (bx >= 56) {                       // ---- weight pack path ----
        const int wb = (bx - 56) * 32 + by;            // 0..255
        if (wb == 0 && tid < 256) { g_sum[tid] = 0.f; g_sumsq[tid] = 0.f; }
        #pragma unroll
        for (int j = 0; j < 4; j++) {
            int idx = wb * 2304 + j * 512 + tid;       // < 589824
            int c  = idx & 255;
            int o  = (idx >> 8) & 255;
            int rs = idx >> 16;
            int r  = rs / 3;
            int s  = rs - 3 * r;
            float v = W[(((size_t)o * 256 + c) * 3 + r) * 3 + s];
            float sv = (v > 0.f) ? 1.f : ((v < 0.f) ? -1.f : 0.f);
            g_wpack[idx] = __float2half(sv);
        }
        if (tid < 256) {
            int idx = wb * 2304 + 2048 + tid;
            int c  = idx & 255;
            int o  = (idx >> 8) & 255;
            int rs = idx >> 16;
            int r  = rs / 3;
            int s  = rs - 3 * r;
            float v = W[(((size_t)o * 256 + c) * 3 + r) * 3 + s];
            float sv = (v > 0.f) ? 1.f : ((v < 0.f) ? -1.f : 0.f);
            g_wpack[idx] = __float2half(sv);
        }
        return;
    }

    // ---- x pack path ----
    const int h = bx, n = by;
    const int wi  = tid & 63;                 // pixel w
    const int gid = tid >> 6;                 // 0..7
    if (wi < 56) {
        #pragma unroll 1
        for (int grp = 0; grp < 4; grp++) {
            const int cq8 = grp * 8 + gid;    // 8-channel group 0..31
            __half tmp[8];
            const float* src = x + (((size_t)n * 256 + cq8 * 8) * 56 + h) * 56 + wi;
            #pragma unroll
            for (int j = 0; j < 8; j++)
                tmp[j] = __float2half(src[(size_t)j * 56 * 56]);
            *(uint4*)&sm[wi][cq8 * 8] = *(uint4*)tmp;
        }
    }
    __syncthreads();
    // read-out: contiguous uint4 per thread, coalesced 16B x 32 lanes to gmem
    #pragma unroll 1
    for (int chunk = tid; chunk < 56 * 32; chunk += 512) {
        int w = chunk >> 5, cq = chunk & 31;
        uint4 v = *(uint4*)&sm[w][cq * 8];
        *(uint4*)(g_xpad + ((size_t)n * PIMG + (h + 1) * PROW + (w + 1)) * CH + cq * 8)
            = v;
    }
}

// ---------------------------------------------------------------------------
// Kernel 2: conv via mma.sync, flat-58 tiling, 2-deep cp.async ring,
// 2 CTAs/SM, fused masked BN stats.  (R10 configuration — at its MMA floor)
// grid (2 ch-tiles, 26 f-tiles, 32 n) = 1664 CTAs, 256 thr (8 warps: 2m x 4n).
// ---------------------------------------------------------------------------
__global__ __launch_bounds__(256, 2) void conv_kernel()
{
    extern __shared__ __align__(128) char dsm[];
    __shared__ float sm_s1[128];
    __shared__ float sm_s2[128];

    const int n0  = blockIdx.x * NT;
    const int f0  = blockIdx.y * 128;          // flat output base
    const int nb  = blockIdx.z;
    const int tid = threadIdx.x;
    const int wid = tid >> 5, lane = tid & 31;
    const int g = lane >> 2, t = lane & 3;
    const int warp_m = wid & 1;                // 64 flat pixels each
    const int warp_n = wid >> 1;               // 32 channels each

    float acc[4][4][4];
    #pragma unroll
    for (int a = 0; a < 4; a++)
        #pragma unroll
        for (int b = 0; b < 4; b++)
            #pragma unroll
            for (int c = 0; c < 4; c++) acc[a][b][c] = 0.f;

    if (tid < 128) { sm_s1[tid] = 0.f; sm_s2[tid] = 0.f; }

    const __half* xp = g_xpad + (size_t)nb * PIMG * CH;

    auto load_stage = [&](int st) {
        char* sb = dsm + (st & 1) * STAGE;
        const int r = st >> 3, kb = st & 7;        // kb: 32-ch block
        const int pix0 = f0 + r * PROW;
        #pragma unroll 1
        for (int i = tid; i < AROWS * 4; i += 256) {
            int row = i >> 2, q = i & 3;
            cp16(su32(sb + AOFF + row * RSTRB + q * 16),
                 xp + (size_t)(pix0 + row) * CH + kb * 32 + q * 8);
        }
        const __half* wp = g_wpack + (size_t)(r * 3) * 65536 + (size_t)n0 * 256 + kb * 32;
        #pragma unroll 1
        for (int i = tid; i < 1536; i += 256) {
            int tap = i >> 9, rem = i & 511, nn = rem >> 2, q = rem & 3;
            cp16(su32(sb + BOFF + (tap * 128 + nn) * RSTRB + q * 16),
                 wp + (size_t)tap * 65536 + (size_t)nn * 256 + q * 8);
        }
        asm volatile("cp.async.commit_group;" ::: "memory");
    };

    auto compute = [&](int st) {
        const char* sb = dsm + (st & 1) * STAGE;
        const __half* sA = (const __half*)(sb + AOFF);
        const __half* sB = (const __half*)(sb + BOFF);
        #pragma unroll
        for (int s = 0; s < 3; s++) {
            #pragma unroll
            for (int kk = 0; kk < 2; kk++) {
                const int c0 = kk * 16 + 2 * t;
                uint32_t af[4][4];
                #pragma unroll
                for (int mt = 0; mt < 4; mt++) {
                    int row = warp_m * 64 + mt * 16 + g + s;
                    af[mt][0] = *(const uint32_t*)(sA + row * RSTRH + c0);
                    af[mt][1] = *(const uint32_t*)(sA + (row + 8) * RSTRH + c0);
                    af[mt][2] = *(const uint32_t*)(sA + row * RSTRH + c0 + 8);
                    af[mt][3] = *(const uint32_t*)(sA + (row + 8) * RSTRH + c0 + 8);
                }
                uint32_t bf[4][2];
                #pragma unroll
                for (int nt = 0; nt < 4; nt++) {
                    int nn = s * 128 + warp_n * 32 + nt * 8 + g;
                    bf[nt][0] = *(const uint32_t*)(sB + nn * RSTRH + c0);
                    bf[nt][1] = *(const uint32_t*)(sB + nn * RSTRH + c0 + 8);
                }
                #pragma unroll
                for (int mt = 0; mt < 4; mt++) {
                    #pragma unroll
                    for (int nt = 0; nt < 4; nt++) {
                        float* cacc = acc[mt][nt];
                        asm volatile(
                          "mma.sync.aligned.m16n8k16.row.col.f32.f16.f16.f32 "
                          "{%0,%1,%2,%3}, {%4,%5,%6,%7}, {%8,%9}, {%0,%1,%2,%3};\n"
                          : "+f"(cacc[0]), "+f"(cacc[1]), "+f"(cacc[2]), "+f"(cacc[3])
                          : "r"(af[mt][0]), "r"(af[mt][1]), "r"(af[mt][2]), "r"(af[mt][3]),
                            "r"(bf[nt][0]), "r"(bf[nt][1]));
                    }
                }
            }
        }
    };

    load_stage(0);
    load_stage(1);
    #pragma unroll 1
    for (int st = 0; st < 24; st++) {
        if (st < 23)
            asm volatile("cp.async.wait_group 1;" ::: "memory");
        else
            asm volatile("cp.async.wait_group 0;" ::: "memory");
        __syncthreads();                 // stage st visible to all warps
        compute(st);
        if (st + 2 < 24) {
            __syncthreads();             // all warps done reading slot st
            load_stage(st + 2);
        }
    }

    // ---- epilogue: acc -> fp16 NHWC (masked) + fused masked BN stats ----
    float s1[4][2], s2[4][2];
    #pragma unroll
    for (int nt = 0; nt < 4; nt++) { s1[nt][0]=s1[nt][1]=s2[nt][0]=s2[nt][1]=0.f; }

    #pragma unroll
    for (int mt = 0; mt < 4; mt++) {
        const int m0 = warp_m * 64 + mt * 16 + g;
        const int fA = f0 + m0;                 // rows g (regs 0,1)
        const int fB = fA + 8;                  // rows g+8 (regs 2,3)
        const int hA = (fA * 565) >> 15, wA = fA - hA * PROW;
        const int hB = (fB * 565) >> 15, wB = fB - hB * PROW;
        const bool vA = (wA < 56) && (hA < 56);
        const bool vB = (wB < 56) && (hB < 56);
        __half* pA = g_ybuf + ((size_t)((nb * HH + hA) * WW + wA)) * CH;
        __half* pB = g_ybuf + ((size_t)((nb * HH + hB) * WW + wB)) * CH;
        #pragma unroll
        for (int nt = 0; nt < 4; nt++) {
            const int ch0 = n0 + warp_n * 32 + nt * 8 + 2 * t;
            float f0v = acc[mt][nt][0], f1v = acc[mt][nt][1];
            float f2v = acc[mt][nt][2], f3v = acc[mt][nt][3];
            if (vA) {
                *(__half2*)(pA + ch0) = __floats2half2_rn(f0v, f1v);
                s1[nt][0] += f0v;  s2[nt][0] += f0v * f0v;
                s1[nt][1] += f1v;  s2[nt][1] += f1v * f1v;
            }
            if (vB) {
                *(__half2*)(pB + ch0) = __floats2half2_rn(f2v, f3v);
                s1[nt][0] += f2v;  s2[nt][0] += f2v * f2v;
                s1[nt][1] += f3v;  s2[nt][1] += f3v * f3v;
            }
        }
    }
    #pragma unroll
    for (int nt = 0; nt < 4; nt++) {
        #pragma unroll
        for (int p = 0; p < 2; p++) {
            #pragma unroll
            for (int m = 4; m < 32; m <<= 1) {
                s1[nt][p] += __shfl_xor_sync(0xffffffffu, s1[nt][p], m);
                s2[nt][p] += __shfl_xor_sync(0xffffffffu, s2[nt][p], m);
            }
        }
    }
    __syncthreads();
    if (g == 0) {
        #pragma unroll
        for (int nt = 0; nt < 4; nt++) {
            #pragma unroll
            for (int p = 0; p < 2; p++) {
                int chl = warp_n * 32 + nt * 8 + 2 * t + p;
                atomicAdd(&sm_s1[chl], s1[nt][p]);
                atomicAdd(&sm_s2[chl], s2[nt][p]);
            }
        }
    }
    __syncthreads();
    if (tid < 128) {
        atomicAdd(&g_sum[n0 + tid],   sm_s1[tid]);
        atomicAdd(&g_sumsq[n0 + tid], sm_s2[tid]);
    }
}

// ---------------------------------------------------------------------------
// Kernel 3: BN finalize + normalize + ReLU + 2x2 maxpool, -> NCHW fp32.
// grid (28 ho, 32 n, 2 ch-halves), 256 threads. 14KB smem/block.
// ---------------------------------------------------------------------------
__global__ __launch_bounds__(256) void pool_kernel(float* __restrict__ out,
                                                   const float* __restrict__ gamma,
                                                   const float* __restrict__ beta)
{
    __shared__ float sm[128 * WO];
    const int ho = blockIdx.x;
    const int n  = blockIdx.y;
    const int z  = blockIdx.z;              // channel half
    const int c2 = threadIdx.x & 63;        // pair within half
    const int p  = threadIdx.x >> 6;        // 0..3

    const float inv = 1.f / (float)NPIX;
    const int ca = z * 128 + 2 * c2, cb = ca + 1;
    float mA = g_sum[ca] * inv, vA = g_sumsq[ca] * inv - mA * mA;
    float scA = gamma[ca] * rsqrtf(vA + 1e-5f);
    float shA = beta[ca] - mA * scA;
    float mB = g_sum[cb] * inv, vB = g_sumsq[cb] * inv - mB * mB;
    float scB = gamma[cb] * rsqrtf(vB + 1e-5f);
    float shB = beta[cb] - mB * scB;

    const __half2* b0 = (const __half2*)(g_ybuf
                        + ((size_t)(n * HH + 2 * ho) * WW) * CH) + z * 64 + c2;
    const __half2* b1 = b0 + (size_t)WW * (CH / 2);

    #pragma unroll
    for (int k = 0; k < 7; k++) {
        const int wo = 4 * k + p;
        float2 a0 = __half22float2(b0[(size_t)(2 * wo)     * (CH / 2)]);
        float2 a1 = __half22float2(b0[(size_t)(2 * wo + 1) * (CH / 2)]);
        float2 a2 = __half22float2(b1[(size_t)(2 * wo)     * (CH / 2)]);
        float2 a3 = __half22float2(b1[(size_t)(2 * wo + 1) * (CH / 2)]);
        float q0 = fmaxf(a0.x * scA + shA, 0.f), q1 = fmaxf(a1.x * scA + shA, 0.f);
        float q2 = fmaxf(a2.x * scA + shA, 0.f), q3 = fmaxf(a3.x * scA + shA, 0.f);
        sm[(2 * c2) * WO + wo] = fmaxf(fmaxf(q0, q1), fmaxf(q2, q3));
        float r0 = fmaxf(a0.y * scB + shB, 0.f), r1 = fmaxf(a1.y * scB + shB, 0.f);
        float r2 = fmaxf(a2.y * scB + shB, 0.f), r3 = fmaxf(a3.y * scB + shB, 0.f);
        sm[(2 * c2 + 1) * WO + wo] = fmaxf(fmaxf(r0, r1), fmaxf(r2, r3));
    }
    __syncthreads();
    for (int i = threadIdx.x; i < 128 * WO; i += 256) {
        int cc = i / WO, wo = i % WO;
        out[(((size_t)n * CH + z * 128 + cc) * HO + ho) * WO + wo] = sm[i];
    }
}

// ---------------------------------------------------------------------------
extern "C" void kernel_launch(void* const* d_in, const int* in_sizes, int n_in,
                              void* d_out, int out_size)
{
    const float* x     = (const float*)d_in[0];
    const float* W     = (const float*)d_in[1];
    const float* gamma = (const float*)d_in[2];
    const float* beta  = (const float*)d_in[3];
    float* out = (float*)d_out;

    prep_kernel<<<dim3(64, BATCH), 512>>>(x, W);

    cudaFuncSetAttribute(conv_kernel, cudaFuncAttributeMaxDynamicSharedMemorySize, DSMEM);
    conv_kernel<<<dim3(2, MT_PER_IMG, BATCH), 256, DSMEM>>>();

    pool_kernel<<<dim3(HO, BATCH, 2), 256>>>(out, gamma, beta);
}

// round 15
// speedup vs baseline: 1.1895x; 1.0690x over previous
#include <cuda_runtime.h>
#include <cuda_fp16.h>
#include <cstdint>

// ---------------- problem constants ----------------
#define BATCH 32
#define CH    256
#define HH    56
#define WW    56
#define HO    28
#define WO    28
#define NPIX  (BATCH*HH*WW)      // 100352 valid output pixels
// flat-57 padded layout: col j of a padded row holds input col j-1
// (col 0 = left pad). Output f = h*57 + w taps input at f + r*57 + s;
// the w+s=57 overflow wraps into the next row's col 0 == required zero pad.
#define PROW  57                 // padded row width
#define PIMG  (58*57)            // 58 padded rows x 57 = 3306 pixels per image
#define MT_PER_IMG 25            // covers f in [0,3200) >= 3191 valid range

// conv tiling: CTA M=128 flat pixels x N=128 ch, K-chunk 32 per stage
#define NT        128
#define AROWS     130            // 128 pixels + 2 shift halo
#define RSTRB     80             // smem row stride bytes (40 halves)
#define RSTRH     40
#define AOFF      0
#define BOFF      (AROWS*RSTRB)                        // 10400
#define STAGE     ((BOFF + 384*RSTRB + 127) & ~127)    // 41216
#define DSMEM     (2*STAGE)                            // 82432 -> 2 CTAs/SM

// prep transpose smem row stride (halves)
#define TSTR      264

// ---------------- static scratch (zero-initialized) ----------------
// slack covers masked-tile halo over-reads past the last image
__device__ __align__(128) __half g_xpad[(size_t)BATCH*PIMG*CH + 32768]; // [n][f][c]
__device__ __align__(128) __half g_wpack[9*256*256];                    // [rs][o][c]
__device__ __align__(128) __half g_ybuf[(size_t)NPIX*CH];               // NHWC conv out
__device__ float g_sum[256], g_sumsq[256];

// ---------------- helpers ----------------
__device__ __forceinline__ uint32_t su32(const void* p) {
    uint32_t a;
    asm("{.reg .u64 t; cvta.to.shared.u64 t, %1; cvt.u32.u64 %0, t;}" : "=r"(a) : "l"(p));
    return a;
}
__device__ __forceinline__ void cp16(uint32_t dst, const void* src) {
    asm volatile("cp.async.cg.shared.global [%0], [%1], 16;" :: "r"(dst), "l"(src));
}

// ---------------------------------------------------------------------------
// Kernel 1 (fused prep, 512 threads): grid (64, 32).
//   bx <  56: transpose-pack x NCHW fp32 -> flat-57 padded [n][(h+1)*57+(w+1)][c]
//   bx >= 56: pack weights -> sign fp16 [rs][o][c]
// ---------------------------------------------------------------------------
__global__ __launch_bounds__(512) void prep_kernel(const float* __restrict__ x,
                                                   const float* __restrict__ W)
{
    __shared__ __half sm[56][TSTR];          // 29568 B
    const int bx = blockIdx.x, by = blockIdx.y;
    const int tid = threadIdx.x;

    if (bx >= 56) {                       // ---- weight pack path ----
        const int wb = (bx - 56) * 32 + by;            // 0..255
        if (wb == 0 && tid < 256) { g_sum[tid] = 0.f; g_sumsq[tid] = 0.f; }
        #pragma unroll
        for (int j = 0; j < 4; j++) {
            int idx = wb * 2304 + j * 512 + tid;       // < 589824
            int c  = idx & 255;
            int o  = (idx >> 8) & 255;
            int rs = idx >> 16;
            int r  = rs / 3;
            int s  = rs - 3 * r;
            float v = W[(((size_t)o * 256 + c) * 3 + r) * 3 + s];
            float sv = (v > 0.f) ? 1.f : ((v < 0.f) ? -1.f : 0.f);
            g_wpack[idx] = __float2half(sv);
        }
        if (tid < 256) {
            int idx = wb * 2304 + 2048 + tid;
            int c  = idx & 255;
            int o  = (idx >> 8) & 255;
            int rs = idx >> 16;
            int r  = rs / 3;
            int s  = rs - 3 * r;
            float v = W[(((size_t)o * 256 + c) * 3 + r) * 3 + s];
            float sv = (v > 0.f) ? 1.f : ((v < 0.f) ? -1.f : 0.f);
            g_wpack[idx] = __float2half(sv);
        }
        return;
    }

    // ---- x pack path (conflict-free smem transpose) ----
    const int h = bx, n = by;
    const int wi  = tid & 63;                 // pixel w
    const int gid = tid >> 6;                 // 0..7
    if (wi < 56) {
        #pragma unroll 1
        for (int grp = 0; grp < 4; grp++) {
            const int cq8 = grp * 8 + gid;    // 8-channel group 0..31
            __half tmp[8];
            const float* src = x + (((size_t)n * 256 + cq8 * 8) * 56 + h) * 56 + wi;
            #pragma unroll
            for (int j = 0; j < 8; j++)
                tmp[j] = __float2half(src[(size_t)j * 56 * 56]);
            *(uint4*)&sm[wi][cq8 * 8] = *(uint4*)tmp;
        }
    }
    __syncthreads();
    #pragma unroll 1
    for (int chunk = tid; chunk < 56 * 32; chunk += 512) {
        int w = chunk >> 5, cq = chunk & 31;
        uint4 v = *(uint4*)&sm[w][cq * 8];
        *(uint4*)(g_xpad + ((size_t)n * PIMG + (h + 1) * PROW + (w + 1)) * CH + cq * 8)
            = v;
    }
}

// ---------------------------------------------------------------------------
// Kernel 2: conv via mma.sync, flat-57 tiling, 2-deep cp.async ring,
// 2 CTAs/SM, fused masked BN stats.
// grid (2 ch-tiles, 25 f-tiles, 32 n) = 1600 CTAs, 256 thr (8 warps: 2m x 4n).
// 24 smem stages = 3 h-taps x 8 blocks of 32 in-ch.
// ---------------------------------------------------------------------------
__global__ __launch_bounds__(256, 2) void conv_kernel()
{
    extern __shared__ __align__(128) char dsm[];
    __shared__ float sm_s1[128];
    __shared__ float sm_s2[128];

    const int n0  = blockIdx.x * NT;
    const int f0  = blockIdx.y * 128;          // flat output base
    const int nb  = blockIdx.z;
    const int tid = threadIdx.x;
    const int wid = tid >> 5, lane = tid & 31;
    const int g = lane >> 2, t = lane & 3;
    const int warp_m = wid & 1;                // 64 flat pixels each
    const int warp_n = wid >> 1;               // 32 channels each

    float acc[4][4][4];
    #pragma unroll
    for (int a = 0; a < 4; a++)
        #pragma unroll
        for (int b = 0; b < 4; b++)
            #pragma unroll
            for (int c = 0; c < 4; c++) acc[a][b][c] = 0.f;

    if (tid < 128) { sm_s1[tid] = 0.f; sm_s2[tid] = 0.f; }

    const __half* xp = g_xpad + (size_t)nb * PIMG * CH;

    auto load_stage = [&](int st) {
        char* sb = dsm + (st & 1) * STAGE;
        const int r = st >> 3, kb = st & 7;        // kb: 32-ch block
        const int pix0 = f0 + r * PROW;
        #pragma unroll 1
        for (int i = tid; i < AROWS * 4; i += 256) {
            int row = i >> 2, q = i & 3;
            cp16(su32(sb + AOFF + row * RSTRB + q * 16),
                 xp + (size_t)(pix0 + row) * CH + kb * 32 + q * 8);
        }
        const __half* wp = g_wpack + (size_t)(r * 3) * 65536 + (size_t)n0 * 256 + kb * 32;
        #pragma unroll 1
        for (int i = tid; i < 1536; i += 256) {
            int tap = i >> 9, rem = i & 511, nn = rem >> 2, q = rem & 3;
            cp16(su32(sb + BOFF + (tap * 128 + nn) * RSTRB + q * 16),
                 wp + (size_t)tap * 65536 + (size_t)nn * 256 + q * 8);
        }
        asm volatile("cp.async.commit_group;" ::: "memory");
    };

    auto compute = [&](int st) {
        const char* sb = dsm + (st & 1) * STAGE;
        const __half* sA = (const __half*)(sb + AOFF);
        const __half* sB = (const __half*)(sb + BOFF);
        #pragma unroll
        for (int s = 0; s < 3; s++) {
            #pragma unroll
            for (int kk = 0; kk < 2; kk++) {
                const int c0 = kk * 16 + 2 * t;
                uint32_t af[4][4];
                #pragma unroll
                for (int mt = 0; mt < 4; mt++) {
                    int row = warp_m * 64 + mt * 16 + g + s;
                    af[mt][0] = *(const uint32_t*)(sA + row * RSTRH + c0);
                    af[mt][1] = *(const uint32_t*)(sA + (row + 8) * RSTRH + c0);
                    af[mt][2] = *(const uint32_t*)(sA + row * RSTRH + c0 + 8);
                    af[mt][3] = *(const uint32_t*)(sA + (row + 8) * RSTRH + c0 + 8);
                }
                uint32_t bf[4][2];
                #pragma unroll
                for (int nt = 0; nt < 4; nt++) {
                    int nn = s * 128 + warp_n * 32 + nt * 8 + g;
                    bf[nt][0] = *(const uint32_t*)(sB + nn * RSTRH + c0);
                    bf[nt][1] = *(const uint32_t*)(sB + nn * RSTRH + c0 + 8);
                }
                #pragma unroll
                for (int mt = 0; mt < 4; mt++) {
                    #pragma unroll
                    for (int nt = 0; nt < 4; nt++) {
                        float* cacc = acc[mt][nt];
                        asm volatile(
                          "mma.sync.aligned.m16n8k16.row.col.f32.f16.f16.f32 "
                          "{%0,%1,%2,%3}, {%4,%5,%6,%7}, {%8,%9}, {%0,%1,%2,%3};\n"
                          : "+f"(cacc[0]), "+f"(cacc[1]), "+f"(cacc[2]), "+f"(cacc[3])
                          : "r"(af[mt][0]), "r"(af[mt][1]), "r"(af[mt][2]), "r"(af[mt][3]),
                            "r"(bf[nt][0]), "r"(bf[nt][1]));
                    }
                }
            }
        }
    };

    load_stage(0);
    load_stage(1);
    #pragma unroll 1
    for (int st = 0; st < 24; st++) {
        if (st < 23)
            asm volatile("cp.async.wait_group 1;" ::: "memory");
        else
            asm volatile("cp.async.wait_group 0;" ::: "memory");
        __syncthreads();                 // stage st visible to all warps
        compute(st);
        if (st + 2 < 24) {
            __syncthreads();             // all warps done reading slot st
            load_stage(st + 2);
        }
    }

    // ---- epilogue: acc -> fp16 NHWC (masked) + fused masked BN stats ----
    float s1[4][2], s2[4][2];
    #pragma unroll
    for (int nt = 0; nt < 4; nt++) { s1[nt][0]=s1[nt][1]=s2[nt][0]=s2[nt][1]=0.f; }

    #pragma unroll
    for (int mt = 0; mt < 4; mt++) {
        const int m0 = warp_m * 64 + mt * 16 + g;
        const int fA = f0 + m0;                 // rows g (regs 0,1)
        const int fB = fA + 8;                  // rows g+8 (regs 2,3)
        // exact floor(f/57) for f < 3200: (f*4600)>>18
        const int hA = (fA * 4600) >> 18, wA = fA - hA * PROW;
        const int hB = (fB * 4600) >> 18, wB = fB - hB * PROW;
        const bool vA = (wA < 56) && (hA < 56);
        const bool vB = (wB < 56) && (hB < 56);
        __half* pA = g_ybuf + ((size_t)((nb * HH + hA) * WW + wA)) * CH;
        __half* pB = g_ybuf + ((size_t)((nb * HH + hB) * WW + wB)) * CH;
        #pragma unroll
        for (int nt = 0; nt < 4; nt++) {
            const int ch0 = n0 + warp_n * 32 + nt * 8 + 2 * t;
            float f0v = acc[mt][nt][0], f1v = acc[mt][nt][1];
            float f2v = acc[mt][nt][2], f3v = acc[mt][nt][3];
            if (vA) {
                *(__half2*)(pA + ch0) = __floats2half2_rn(f0v, f1v);
                s1[nt][0] += f0v;  s2[nt][0] += f0v * f0v;
                s1[nt][1] += f1v;  s2[nt][1] += f1v * f1v;
            }
            if (vB) {
                *(__half2*)(pB + ch0) = __floats2half2_rn(f2v, f3v);
                s1[nt][0] += f2v;  s2[nt][0] += f2v * f2v;
                s1[nt][1] += f3v;  s2[nt][1] += f3v * f3v;
            }
        }
    }
    #pragma unroll
    for (int nt = 0; nt < 4; nt++) {
        #pragma unroll
        for (int p = 0; p < 2; p++) {
            #pragma unroll
            for (int m = 4; m < 32; m <<= 1) {
                s1[nt][p] += __shfl_xor_sync(0xffffffffu, s1[nt][p], m);
                s2[nt][p] += __shfl_xor_sync(0xffffffffu, s2[nt][p], m);
            }
        }
    }
    __syncthreads();
    if (g == 0) {
        #pragma unroll
        for (int nt = 0; nt < 4; nt++) {
            #pragma unroll
            for (int p = 0; p < 2; p++) {
                int chl = warp_n * 32 + nt * 8 + 2 * t + p;
                atomicAdd(&sm_s1[chl], s1[nt][p]);
                atomicAdd(&sm_s2[chl], s2[nt][p]);
            }
        }
    }
    __syncthreads();
    if (tid < 128) {
        atomicAdd(&g_sum[n0 + tid],   sm_s1[tid]);
        atomicAdd(&g_sumsq[n0 + tid], sm_s2[tid]);
    }
}

// ---------------------------------------------------------------------------
// Kernel 3: BN finalize + normalize + ReLU + 2x2 maxpool, -> NCHW fp32.
// grid (28 ho, 32 n, 2 ch-halves), 256 threads. 14KB smem/block.
// ---------------------------------------------------------------------------
__global__ __launch_bounds__(256) void pool_kernel(float* __restrict__ out,
                                                   const float* __restrict__ gamma,
                                                   const float* __restrict__ beta)
{
    __shared__ float sm[128 * WO];
    const int ho = blockIdx.x;
    const int n  = blockIdx.y;
    const int z  = blockIdx.z;              // channel half
    const int c2 = threadIdx.x & 63;        // pair within half
    const int p  = threadIdx.x >> 6;        // 0..3

    const float inv = 1.f / (float)NPIX;
    const int ca = z * 128 + 2 * c2, cb = ca + 1;
    float mA = g_sum[ca] * inv, vA = g_sumsq[ca] * inv - mA * mA;
    float scA = gamma[ca] * rsqrtf(vA + 1e-5f);
    float shA = beta[ca] - mA * scA;
    float mB = g_sum[cb] * inv, vB = g_sumsq[cb] * inv - mB * mB;
    float scB = gamma[cb] * rsqrtf(vB + 1e-5f);
    float shB = beta[cb] - mB * scB;

    const __half2* b0 = (const __half2*)(g_ybuf
                        + ((size_t)(n * HH + 2 * ho) * WW) * CH) + z * 64 + c2;
    const __half2* b1 = b0 + (size_t)WW * (CH / 2);

    #pragma unroll
    for (int k = 0; k < 7; k++) {
        const int wo = 4 * k + p;
        float2 a0 = __half22float2(b0[(size_t)(2 * wo)     * (CH / 2)]);
        float2 a1 = __half22float2(b0[(size_t)(2 * wo + 1) * (CH / 2)]);
        float2 a2 = __half22float2(b1[(size_t)(2 * wo)     * (CH / 2)]);
        float2 a3 = __half22float2(b1[(size_t)(2 * wo + 1) * (CH / 2)]);
        float q0 = fmaxf(a0.x * scA + shA, 0.f), q1 = fmaxf(a1.x * scA + shA, 0.f);
        float q2 = fmaxf(a2.x * scA + shA, 0.f), q3 = fmaxf(a3.x * scA + shA, 0.f);
        sm[(2 * c2) * WO + wo] = fmaxf(fmaxf(q0, q1), fmaxf(q2, q3));
        float r0 = fmaxf(a0.y * scB + shB, 0.f), r1 = fmaxf(a1.y * scB + shB, 0.f);
        float r2 = fmaxf(a2.y * scB + shB, 0.f), r3 = fmaxf(a3.y * scB + shB, 0.f);
        sm[(2 * c2 + 1) * WO + wo] = fmaxf(fmaxf(r0, r1), fmaxf(r2, r3));
    }
    __syncthreads();
    for (int i = threadIdx.x; i < 128 * WO; i += 256) {
        int cc = i / WO, wo = i % WO;
        out[(((size_t)n * CH + z * 128 + cc) * HO + ho) * WO + wo] = sm[i];
    }
}

// ---------------------------------------------------------------------------
extern "C" void kernel_launch(void* const* d_in, const int* in_sizes, int n_in,
                              void* d_out, int out_size)
{
    const float* x     = (const float*)d_in[0];
    const float* W     = (const float*)d_in[1];
    const float* gamma = (const float*)d_in[2];
    const float* beta  = (const float*)d_in[3];
    float* out = (float*)d_out;

    prep_kernel<<<dim3(64, BATCH), 512>>>(x, W);

    cudaFuncSetAttribute(conv_kernel, cudaFuncAttributeMaxDynamicSharedMemorySize, DSMEM);
    conv_kernel<<<dim3(2, MT_PER_IMG, BATCH), 256, DSMEM>>>();

    pool_kernel<<<dim3(HO, BATCH, 2), 256>>>(out, gamma, beta);
}